// round 17
// baseline (speedup 1.0000x reference)
#include <cuda_runtime.h>
#include <cuda_bf16.h>
#include <cuda_fp16.h>
#include <stdint.h>
#include <math.h>

typedef unsigned long long u64;
typedef unsigned int u32;

#define T_TOK 4096
#define HDIM  1024
#define IDIM  2048
#define NEXP  8
#define SLOTS (2 * T_TOK)
#define ROWS_ALL (SLOTS + T_TOK)   // expert slots + shared rows

// ======================= scratch (device globals) =======================
__device__ __align__(16) __half g_x16[(size_t)T_TOK * HDIM];
// 9 "experts": 0..7 routed (gate/up interleaved), 8 = shared expert
__device__ __align__(16) __half g_eguT[(size_t)(NEXP + 1) * (2 * IDIM) * HDIM];
__device__ __align__(16) __half g_edT16[(size_t)(NEXP + 1) * HDIM * IDIM];
// h rows: [0,SLOTS) expert slots, [SLOTS,SLOTS+T_TOK) shared tokens
__device__ __align__(16) __half g_h16[(size_t)ROWS_ALL * IDIM];
__device__ float g_eout[(size_t)ROWS_ALL * HDIM];

// router folding
__device__ float g_w2[HDIM * NEXP];      // tpw @ gw
__device__ float g_bconst[NEXP];         // tpb @ gw

// routing
__device__ int   g_tok_e[T_TOK * 2];
__device__ float g_tok_w[T_TOK * 2];
__device__ int   g_tok_slot[T_TOK * 2];
__device__ int   g_counts[NEXP];
__device__ int   g_offsets[NEXP];
__device__ int   g_cursor[NEXP];
__device__ int   g_list_tok[SLOTS];
__device__ float g_list_w[SLOTS];

// ======================= PTX helpers (sm_80-era, compute_103-safe) =======================
__device__ __forceinline__ u32 smem_u32(const void* p) {
    u32 a;
    asm("{ .reg .u64 t; cvta.to.shared.u64 t, %1; cvt.u32.u64 %0, t; }" : "=r"(a) : "l"(p));
    return a;
}
__device__ __forceinline__ void cpa16(u32 dst, const void* src) {
    asm volatile("cp.async.cg.shared.global [%0], [%1], 16;"
                 :: "r"(dst), "l"(src) : "memory");
}
__device__ __forceinline__ void cpa_commit() {
    asm volatile("cp.async.commit_group;" ::: "memory");
}
__device__ __forceinline__ void ldsm4(u32* r, u32 addr) {
    asm volatile("ldmatrix.sync.aligned.m8n8.x4.shared.b16 {%0,%1,%2,%3}, [%4];"
                 : "=r"(r[0]), "=r"(r[1]), "=r"(r[2]), "=r"(r[3]) : "r"(addr));
}
__device__ __forceinline__ void mma_f16(float* c, const u32* a, u32 b0, u32 b1) {
    asm volatile("mma.sync.aligned.m16n8k16.row.col.f32.f16.f16.f32 "
                 "{%0,%1,%2,%3}, {%4,%5,%6,%7}, {%8,%9}, {%0,%1,%2,%3};"
                 : "+f"(c[0]), "+f"(c[1]), "+f"(c[2]), "+f"(c[3])
                 : "r"(a[0]), "r"(a[1]), "r"(a[2]), "r"(a[3]), "r"(b0), "r"(b1));
}

// ======================= small kernels =======================
__global__ void k_init() {
    int i = threadIdx.x;
    if (i < NEXP) { g_counts[i] = 0; g_cursor[i] = 0; }
}

__global__ void k_cvt16(const float* __restrict__ S, __half* __restrict__ H, int n4) {
    int i = blockIdx.x * blockDim.x + threadIdx.x;
    if (i >= n4) return;
    float4 v = ((const float4*)S)[i];
    union { __half b[4]; uint2 u; } uh;
    uh.b[0] = __float2half_rn(v.x); uh.b[1] = __float2half_rn(v.y);
    uh.b[2] = __float2half_rn(v.z); uh.b[3] = __float2half_rn(v.w);
    ((uint2*)H)[i] = uh.u;
}

// transpose + single fp16: W [K,N] (+z*srcZ) -> T rows (n*rowmul + phase) (+z*dstZ)
__global__ void k_t16(const float* __restrict__ W, __half* __restrict__ T,
                      int K, int N, size_t srcZ, size_t dstZ, int rowmul, int phase) {
    W += (size_t)blockIdx.z * srcZ; T += (size_t)blockIdx.z * dstZ;
    __shared__ float t[32][33];
    int k0 = blockIdx.y * 32, n0 = blockIdx.x * 32;
    int tx = threadIdx.x, ty = threadIdx.y;
#pragma unroll
    for (int q = 0; q < 4; q++)
        t[ty + 8 * q][tx] = W[(size_t)(k0 + ty + 8 * q) * N + n0 + tx];
    __syncthreads();
#pragma unroll
    for (int q = 0; q < 4; q++) {
        int n = ty + 8 * q;
        T[(size_t)((n0 + n) * rowmul + phase) * K + k0 + tx] = __float2half_rn(t[tx][n]);
    }
}

// W2[h,e] = sum_k tpw[h,k] * gw[k,e]
__global__ void k_w2(const float* __restrict__ tpw, const float* __restrict__ gw) {
    int h = (blockIdx.x * blockDim.x + threadIdx.x) >> 5;
    int lane = threadIdx.x & 31;
    if (h >= HDIM) return;
    const float* row = tpw + (size_t)h * HDIM;
    float acc[8] = {0.f,0.f,0.f,0.f,0.f,0.f,0.f,0.f};
    for (int k = lane; k < HDIM; k += 32) {
        float v = row[k];
        float4 w0 = *(const float4*)(gw + (size_t)k * 8);
        float4 w1 = *(const float4*)(gw + (size_t)k * 8 + 4);
        acc[0] += v * w0.x; acc[1] += v * w0.y; acc[2] += v * w0.z; acc[3] += v * w0.w;
        acc[4] += v * w1.x; acc[5] += v * w1.y; acc[6] += v * w1.z; acc[7] += v * w1.w;
    }
#pragma unroll
    for (int o = 16; o; o >>= 1)
#pragma unroll
        for (int e = 0; e < 8; e++) acc[e] += __shfl_down_sync(0xffffffffu, acc[e], o);
    if (lane == 0) {
#pragma unroll
        for (int e = 0; e < 8; e++) g_w2[h * 8 + e] = acc[e];
    }
}

// bconst[e] = sum_h tpb[h] * gw[h,e]
__global__ void k_bconst(const float* __restrict__ tpb, const float* __restrict__ gw) {
    __shared__ float red[256][8];
    int tid = threadIdx.x;
    float acc[8] = {0.f,0.f,0.f,0.f,0.f,0.f,0.f,0.f};
    for (int h = tid; h < HDIM; h += 256) {
        float b = tpb[h];
        float4 w0 = *(const float4*)(gw + (size_t)h * 8);
        float4 w1 = *(const float4*)(gw + (size_t)h * 8 + 4);
        acc[0] += b * w0.x; acc[1] += b * w0.y; acc[2] += b * w0.z; acc[3] += b * w0.w;
        acc[4] += b * w1.x; acc[5] += b * w1.y; acc[6] += b * w1.z; acc[7] += b * w1.w;
    }
#pragma unroll
    for (int e = 0; e < 8; e++) red[tid][e] = acc[e];
    __syncthreads();
    for (int s = 128; s; s >>= 1) {
        if (tid < s)
#pragma unroll
            for (int e = 0; e < 8; e++) red[tid][e] += red[tid + s][e];
        __syncthreads();
    }
    if (tid < 8) g_bconst[tid] = red[0][tid];
}

// fused gate: logits = x@gw + tc@W2 + bconst; softmax; top-2; histogram
__global__ void k_gate(const float* __restrict__ x, const float* __restrict__ tcx,
                       const float* __restrict__ gw) {
    int t = (blockIdx.x * blockDim.x + threadIdx.x) >> 5;
    int lane = threadIdx.x & 31;
    if (t >= T_TOK) return;
    const float* xr = x + (size_t)t * HDIM;
    const float* tr = tcx + (size_t)t * HDIM;
    float acc[8] = {0.f,0.f,0.f,0.f,0.f,0.f,0.f,0.f};
    for (int h = lane; h < HDIM; h += 32) {
        float xv = xr[h];
        float tv = tr[h];
        float4 w0 = *(const float4*)(gw + (size_t)h * 8);
        float4 w1 = *(const float4*)(gw + (size_t)h * 8 + 4);
        float4 m0 = *(const float4*)(g_w2 + (size_t)h * 8);
        float4 m1 = *(const float4*)(g_w2 + (size_t)h * 8 + 4);
        acc[0] += xv * w0.x + tv * m0.x; acc[1] += xv * w0.y + tv * m0.y;
        acc[2] += xv * w0.z + tv * m0.z; acc[3] += xv * w0.w + tv * m0.w;
        acc[4] += xv * w1.x + tv * m1.x; acc[5] += xv * w1.y + tv * m1.y;
        acc[6] += xv * w1.z + tv * m1.z; acc[7] += xv * w1.w + tv * m1.w;
    }
#pragma unroll
    for (int o = 16; o; o >>= 1)
#pragma unroll
        for (int e = 0; e < 8; e++) acc[e] += __shfl_down_sync(0xffffffffu, acc[e], o);
    if (lane == 0) {
#pragma unroll
        for (int e = 0; e < 8; e++) acc[e] += g_bconst[e];
        float mx = acc[0];
#pragma unroll
        for (int e = 1; e < 8; e++) mx = fmaxf(mx, acc[e]);
        float p[8]; float Z = 0.f;
#pragma unroll
        for (int e = 0; e < 8; e++) { p[e] = __expf(acc[e] - mx); Z += p[e]; }
        float rZ = 1.f / Z;
#pragma unroll
        for (int e = 0; e < 8; e++) p[e] *= rZ;
        int i0 = 0; float p0 = p[0];
#pragma unroll
        for (int e = 1; e < 8; e++) if (p[e] > p0) { p0 = p[e]; i0 = e; }
        int i1 = -1; float p1 = -1.f;
#pragma unroll
        for (int e = 0; e < 8; e++) if (e != i0 && p[e] > p1) { p1 = p[e]; i1 = e; }
        float s = 1.f / (p0 + p1 + 1e-5f);
        g_tok_e[2*t] = i0;     g_tok_w[2*t] = p0 * s;
        g_tok_e[2*t+1] = i1;   g_tok_w[2*t+1] = p1 * s;
        atomicAdd(&g_counts[i0], 1); atomicAdd(&g_counts[i1], 1);
    }
}

__global__ void k_offsets() {
    if (threadIdx.x == 0) {
        int s = 0;
        for (int e = 0; e < NEXP; e++) { g_offsets[e] = s; s += g_counts[e]; g_cursor[e] = 0; }
    }
}

__global__ void k_place() {
    int t = blockIdx.x * blockDim.x + threadIdx.x;
    if (t >= T_TOK) return;
#pragma unroll
    for (int k = 0; k < 2; k++) {
        int e = g_tok_e[2*t + k];
        int pos = g_offsets[e] + atomicAdd(&g_cursor[e], 1);
        g_list_tok[pos] = t;
        g_list_w[pos] = g_tok_w[2*t + k];
        g_tok_slot[2*t + k] = pos;
    }
}

// out[t] = eout[SLOTS+t] + eout[s0] + eout[s1]   (same add order as before)
__global__ void k_combine(float* __restrict__ out) {
    int gid = blockIdx.x * blockDim.x + threadIdx.x;
    int t = gid / (HDIM / 4);
    int c = (gid % (HDIM / 4)) * 4;
    if (t >= T_TOK) return;
    int s0 = g_tok_slot[2*t], s1 = g_tok_slot[2*t+1];
    float4 o = *(const float4*)(g_eout + (size_t)(SLOTS + t) * HDIM + c);
    float4 a = *(const float4*)(g_eout + (size_t)s0 * HDIM + c);
    float4 b = *(const float4*)(g_eout + (size_t)s1 * HDIM + c);
    o.x += a.x + b.x; o.y += a.y + b.y; o.z += a.z + b.z; o.w += a.w + b.w;
    *(float4*)(out + (size_t)t * HDIM + c) = o;
}

// ======================= fp16 single-pass GEMM (merged 9-expert) =======================
// grid z in [0, NEXP]: z<8 routed expert, z==8 shared expert (dense, off=SLOTS, w=1).
// mode 1 (gate+up): A rows gathered tokens (z<8) or identity (z=8);
//                   epilogue SwiGLU -> Ch rows off+row (Nld interleaved gate/up).
// mode 2 (down):    A rows off+row of h16; plain fp32 store -> Cf rows off+row.
#define CH_K    32
#define QROWB   80
#define QA_MATB (256 * QROWB)
#define QOFF_B  QA_MATB
#define QSTGB   (QA_MATB + 128 * QROWB) // 30720
#define QNSTG   4
#define GEMM16_SMEM (QNSTG * QSTGB)     // 122880

__global__ __launch_bounds__(512, 1) void k_gemm16(
    const __half* __restrict__ A, const __half* __restrict__ B,
    float* __restrict__ Cf, __half* __restrict__ Ch,
    int Kdim, int Nld, int mode)
{
    const int z = blockIdx.z;
    const bool se = (z == NEXP);
    const int cnt = se ? T_TOK : g_counts[z];
    const int off = se ? SLOTS : g_offsets[z];
    B += (size_t)z * Nld * Kdim;

    const int m0 = blockIdx.y * 256;
    if (m0 >= cnt) return;
    const int n0 = blockIdx.x * 128;

    extern __shared__ char smem[];
    __shared__ int s_arow[256];
    const u32 sb = smem_u32(smem);
    const int tid = threadIdx.x;

    if (tid < 256) {
        int mr = m0 + tid; if (mr > cnt - 1) mr = cnt - 1;
        int gr;
        if (mode == 1) gr = se ? mr : g_list_tok[off + mr];
        else           gr = off + mr;
        s_arow[tid] = gr;
    }
    __syncthreads();

    const int nc = Kdim / CH_K;

#define QLOAD(c) do {                                                          \
        int _k0 = (c) * CH_K;                                                  \
        u32 _db = sb + ((c) % QNSTG) * QSTGB;                                  \
        if (tid < 256) {                                                       \
            const __half* _pa = A + (size_t)s_arow[tid] * Kdim + _k0;          \
            u32 _da = _db + tid * QROWB;                                       \
            cpa16(_da,      _pa); cpa16(_da + 16, _pa + 8);                    \
            cpa16(_da + 32, _pa + 16); cpa16(_da + 48, _pa + 24);              \
        } else {                                                               \
            int _r = (tid - 256) >> 1, _h = (tid - 256) & 1;                   \
            const __half* _p = B + (size_t)(n0 + _r) * Kdim + _k0 + _h * 16;   \
            u32 _d = _db + QOFF_B + _r * QROWB + _h * 32;                      \
            cpa16(_d, _p); cpa16(_d + 16, _p + 8);                             \
        }                                                                      \
    } while (0)

    float acc[4][4][4];
#pragma unroll
    for (int i = 0; i < 4; i++)
#pragma unroll
        for (int j = 0; j < 4; j++)
#pragma unroll
            for (int q = 0; q < 4; q++) acc[i][j][q] = 0.f;

    const int wid = tid >> 5, lane = tid & 31;
    const int wm = wid >> 2, wn = wid & 3;
    const int fr = lane & 15;
    const int fk = ((lane >> 4) & 1) * 16;

    QLOAD(0); cpa_commit();
    QLOAD(1); cpa_commit();
    QLOAD(2); cpa_commit();

    for (int c = 0; c < nc; c++) {
        if (c + 2 < nc)      asm volatile("cp.async.wait_group 2;" ::: "memory");
        else if (c + 1 < nc) asm volatile("cp.async.wait_group 1;" ::: "memory");
        else                 asm volatile("cp.async.wait_group 0;" ::: "memory");
        __syncthreads();
        if (c + 3 < nc) { QLOAD(c + 3); cpa_commit(); }

        const u32 ab = sb + (c % QNSTG) * QSTGB;
        const u32 bb = ab + QOFF_B;

#pragma unroll
        for (int kk = 0; kk < 2; kk++) {
            const int kb = kk * 32;
            u32 af[4][4], bf[2][4];
#pragma unroll
            for (int i = 0; i < 4; i++) {
                u32 ad = ab + (wm * 64 + i * 16 + fr) * QROWB + kb + fk;
                ldsm4(af[i], ad);
            }
#pragma unroll
            for (int j = 0; j < 2; j++) {
                u32 bd = bb + (wn * 32 + j * 16 + fr) * QROWB + kb + fk;
                ldsm4(bf[j], bd);
            }
#pragma unroll
            for (int i = 0; i < 4; i++)
#pragma unroll
                for (int nt = 0; nt < 4; nt++) {
                    int j = nt >> 1, t = nt & 1;
                    mma_f16(acc[i][nt], af[i], bf[j][t], bf[j][t + 2]);
                }
        }
    }

#pragma unroll
    for (int i = 0; i < 4; i++) {
#pragma unroll
        for (int h = 0; h < 2; h++) {
            int lr = wm * 64 + i * 16 + (lane >> 2) + h * 8;
            if (m0 + lr < cnt) {
                int orow = off + m0 + lr;
                if (mode == 2) {
                    float* crow = Cf + (size_t)orow * Nld + n0 + wn * 32;
#pragma unroll
                    for (int nt = 0; nt < 4; nt++) {
                        int col = nt * 8 + (lane & 3) * 2;
                        *(float2*)(crow + col) =
                            make_float2(acc[i][nt][h * 2], acc[i][nt][h * 2 + 1]);
                    }
                } else {
                    float w = se ? 1.0f : g_list_w[orow];
                    __half* hrow = Ch + (size_t)orow * (Nld / 2) + (n0 + wn * 32) / 2;
#pragma unroll
                    for (int nt = 0; nt < 4; nt++) {
                        int hcol = nt * 4 + (lane & 3);
                        float gv = acc[i][nt][h * 2];
                        float uv = acc[i][nt][h * 2 + 1];
                        float sig = 1.f / (1.f + __expf(-gv));
                        hrow[hcol] = __float2half_rn(w * (gv * sig) * uv);
                    }
                }
            }
        }
    }
#undef QLOAD
}

// ======================= launch =======================
static cudaStream_t g_s2 = nullptr;
static cudaEvent_t  g_evF = nullptr;
static cudaEvent_t  g_evJ = nullptr;
static cudaEvent_t  g_evW = nullptr;

extern "C" void kernel_launch(void* const* d_in, const int* in_sizes, int n_in,
                              void* d_out, int out_size) {
    const float* x   = (const float*)d_in[0];
    const float* tcx = (const float*)d_in[1];
    const float* tpw = (const float*)d_in[2];
    const float* tpb = (const float*)d_in[3];
    const float* gw  = (const float*)d_in[4];
    const float* eg  = (const float*)d_in[5];
    const float* eu  = (const float*)d_in[6];
    const float* ed  = (const float*)d_in[7];
    const float* sg  = (const float*)d_in[8];
    const float* su  = (const float*)d_in[9];
    const float* sd  = (const float*)d_in[10];
    float* out = (float*)d_out;

    if (!g_s2) {
        cudaStreamCreateWithFlags(&g_s2, cudaStreamNonBlocking);
        cudaEventCreateWithFlags(&g_evF, cudaEventDisableTiming);
        cudaEventCreateWithFlags(&g_evJ, cudaEventDisableTiming);
        cudaEventCreateWithFlags(&g_evW, cudaEventDisableTiming);
        cudaFuncSetAttribute(k_gemm16, cudaFuncAttributeMaxDynamicSharedMemorySize, GEMM16_SMEM);
    }

    __half *x16, *eguT, *edT16, *h16;
    float *eout;
    cudaGetSymbolAddress((void**)&x16, g_x16);
    cudaGetSymbolAddress((void**)&eguT, g_eguT);
    cudaGetSymbolAddress((void**)&edT16, g_edT16);
    cudaGetSymbolAddress((void**)&h16, g_h16);
    cudaGetSymbolAddress((void**)&eout, g_eout);

    const size_t GU_Z = (size_t)2 * IDIM * HDIM;   // per-expert gate/up block
    const size_t DN_Z = (size_t)HDIM * IDIM;       // per-expert down block

    dim3 wb(32, 8);
    int n4 = T_TOK * HDIM / 4;

    // ---- fork: B = routing chain, then down-weight transposes ----
    cudaEventRecord(g_evF, 0);
    cudaStreamWaitEvent(g_s2, g_evF, 0);
    k_init<<<1, 32, 0, g_s2>>>();
    k_w2<<<HDIM / 8, 256, 0, g_s2>>>(tpw, gw);
    k_bconst<<<1, 256, 0, g_s2>>>(tpb, gw);
    k_gate<<<T_TOK / 8, 256, 0, g_s2>>>(x, tcx, gw);
    k_offsets<<<1, 32, 0, g_s2>>>();
    k_place<<<T_TOK / 256, 256, 0, g_s2>>>();
    cudaEventRecord(g_evJ, g_s2);
    // down-proj weights (needed only by GEMM2) — overlap with A's transposes + GEMM1
    k_t16<<<dim3(HDIM/32, IDIM/32, NEXP), wb, 0, g_s2>>>(ed, edT16, IDIM, HDIM,
        (size_t)IDIM * HDIM, DN_Z, 1, 0);
    k_t16<<<dim3(HDIM/32, IDIM/32, 1), wb, 0, g_s2>>>(sd, edT16 + (size_t)NEXP * DN_Z,
        IDIM, HDIM, 0, 0, 1, 0);
    cudaEventRecord(g_evW, g_s2);

    // ---- A: activation conversion + gate/up weight transposes ----
    k_cvt16<<<n4 / 256, 256>>>(x, x16, n4);
    k_t16<<<dim3(IDIM/32, HDIM/32, NEXP), wb>>>(eg, eguT, HDIM, IDIM,
        (size_t)HDIM * IDIM, GU_Z, 2, 0);
    k_t16<<<dim3(IDIM/32, HDIM/32, NEXP), wb>>>(eu, eguT, HDIM, IDIM,
        (size_t)HDIM * IDIM, GU_Z, 2, 1);
    k_t16<<<dim3(IDIM/32, HDIM/32, 1), wb>>>(sg, eguT + (size_t)NEXP * GU_Z,
        HDIM, IDIM, 0, 0, 2, 0);
    k_t16<<<dim3(IDIM/32, HDIM/32, 1), wb>>>(su, eguT + (size_t)NEXP * GU_Z,
        HDIM, IDIM, 0, 0, 2, 1);

    // ---- join routing, then merged GEMMs ----
    cudaStreamWaitEvent(0, g_evJ, 0);
    k_gemm16<<<dim3(2*IDIM/128, SLOTS/256, NEXP + 1), 512, GEMM16_SMEM>>>(
        x16, eguT, nullptr, h16, HDIM, 2*IDIM, 1);
    cudaStreamWaitEvent(0, g_evW, 0);
    k_gemm16<<<dim3(HDIM/128, SLOTS/256, NEXP + 1), 512, GEMM16_SMEM>>>(
        h16, edT16, eout, nullptr, IDIM, HDIM, 2);
    k_combine<<<(T_TOK * (HDIM / 4)) / 256, 256>>>(out);
}